// round 5
// baseline (speedup 1.0000x reference)
#include <cuda_runtime.h>
#include <math.h>

// ---------------------------------------------------------------------------
// CausalEdgeAttention — algebraically reduced, tensor-core main pass:
//   out = edge_attr + relu(nc@W1eff + b1) @ Meff + c2
//   nc    = nf[src]+nf[tgt]            (0.5 folded into W1eff = 0.5*n_W1)
//   Meff  = 0.5 * diag(scale) * (n_W2 @ Wv @ Wo @ Wp)
//   c2    = 0.5 * (b2@R2 + bv@R1 + bo@Wp + bp + shift@M)
//   scale = gamma*rsqrt(var+eps), shift = beta - mu*scale (BN stats of h1)
// Edge encoder in the reference is dead code -> skipped.
// Main pass: per warp-tile of 16 edges, 32 n-chunks; each chunk:
//   HMMA(z = nc@W1 + b1) -> relu -> shfl repack C-frag->A-frag -> HMMA(out += h1@Meff)
// ---------------------------------------------------------------------------

#define HDIM 256
#define DDIM 8
#define NBLKA 512
#define TPW 4            // tiles per warp in main

typedef unsigned long long u64;
typedef unsigned int u32;

__device__ __forceinline__ u64 pk(float lo, float hi) {
    u64 r; asm("mov.b64 %0,{%1,%2};" : "=l"(r) : "f"(lo), "f"(hi)); return r;
}
__device__ __forceinline__ void upk(u64 v, float& lo, float& hi) {
    asm("mov.b64 {%0,%1},%2;" : "=f"(lo), "=f"(hi) : "l"(v));
}
__device__ __forceinline__ u64 f2mul(u64 a, u64 b) {
    u64 d; asm("mul.rn.f32x2 %0,%1,%2;" : "=l"(d) : "l"(a), "l"(b)); return d;
}
__device__ __forceinline__ u64 f2fma(u64 a, u64 b, u64 c) {
    u64 d; asm("fma.rn.f32x2 %0,%1,%2,%3;" : "=l"(d) : "l"(a), "l"(b), "l"(c)); return d;
}

// ------------------------- scratch (device globals; no allocs) -------------
__device__ float2 g_ps[NBLKA * HDIM];  // BN partials (sum, sumsq)
__device__ float2 g_zB[1024];          // z-GEMM B-frags: [32 chunks][32 lanes]{b0,b1}
__device__ float2 g_mB[1024];          // M-GEMM B-frags
__device__ float  g_c2[DDIM];

// ------------------------- pass A: BN statistics of h1 (scalar f32x2) ------
__global__ void __launch_bounds__(256) stats_kernel(const float* __restrict__ nf,
                                                    const int* __restrict__ ei0,
                                                    const int* __restrict__ ei1,
                                                    const float* __restrict__ W1,
                                                    const float* __restrict__ b1,
                                                    int E) {
    __shared__ u64 ncs[256 * 4];
    int t = threadIdx.x;
    u64 w0 = pk(0.5f * W1[0 * HDIM + t], 0.5f * W1[1 * HDIM + t]);
    u64 w1 = pk(0.5f * W1[2 * HDIM + t], 0.5f * W1[3 * HDIM + t]);
    u64 w2 = pk(0.5f * W1[4 * HDIM + t], 0.5f * W1[5 * HDIM + t]);
    u64 w3 = pk(0.5f * W1[6 * HDIM + t], 0.5f * W1[7 * HDIM + t]);
    float b1h = b1[t];
    float sum = 0.f, sq = 0.f;
    const float4* nfp = (const float4*)nf;

    for (int base = blockIdx.x * 256; base < E; base += gridDim.x * 256) {
        int nval = min(256, E - base);
        __syncthreads();
        if (t < nval) {
            int e = base + t;
            int s = __ldg(ei0 + e), g = __ldg(ei1 + e);
            float4 a0 = __ldg(nfp + 2 * s), a1 = __ldg(nfp + 2 * s + 1);
            float4 c0 = __ldg(nfp + 2 * g), c1 = __ldg(nfp + 2 * g + 1);
            ncs[t * 4 + 0] = pk(a0.x + c0.x, a0.y + c0.y);
            ncs[t * 4 + 1] = pk(a0.z + c0.z, a0.w + c0.w);
            ncs[t * 4 + 2] = pk(a1.x + c1.x, a1.y + c1.y);
            ncs[t * 4 + 3] = pk(a1.z + c1.z, a1.w + c1.w);
        }
        __syncthreads();
#pragma unroll 4
        for (int j = 0; j < nval; j++) {
            u64 s_ = f2mul(ncs[j * 4 + 0], w0);
            s_ = f2fma(ncs[j * 4 + 1], w1, s_);
            s_ = f2fma(ncs[j * 4 + 2], w2, s_);
            s_ = f2fma(ncs[j * 4 + 3], w3, s_);
            float lo, hi; upk(s_, lo, hi);
            float h1 = fmaxf(lo + hi + b1h, 0.f);
            sum += h1;
            sq = fmaf(h1, h1, sq);
        }
    }
    g_ps[blockIdx.x * HDIM + t] = make_float2(sum, sq);
}

// ------------------------- setup: folds + BN finalize + frag packing -------
// single block, 256 threads. thread t owns row h=t of every [256,8] product.
__device__ __forceinline__ void fold_rows(const float* __restrict__ A,
                                          const float* Bs, float* Os) {
    int t = threadIdx.x;
    const u64* Bp = (const u64*)Bs;   // pairs [k][p], broadcast reads
    const float* Ar = A + t * HDIM;
    u64 a0 = 0, a1 = 0, a2 = 0, a3 = 0;
#pragma unroll 8
    for (int k = 0; k < HDIM; k++) {
        float a = __ldg(Ar + k);
        u64 aa = pk(a, a);
        a0 = f2fma(aa, Bp[k * 4 + 0], a0);
        a1 = f2fma(aa, Bp[k * 4 + 1], a1);
        a2 = f2fma(aa, Bp[k * 4 + 2], a2);
        a3 = f2fma(aa, Bp[k * 4 + 3], a3);
    }
    u64* Op = (u64*)Os;
    Op[t * 4 + 0] = a0; Op[t * 4 + 1] = a1;
    Op[t * 4 + 2] = a2; Op[t * 4 + 3] = a3;
}

__global__ void __launch_bounds__(256) setup_kernel(const float* __restrict__ Wo,
                                                    const float* __restrict__ Wp,
                                                    const float* __restrict__ Wv,
                                                    const float* __restrict__ nW2,
                                                    const float* __restrict__ nW1,
                                                    const float* __restrict__ gamma,
                                                    const float* __restrict__ beta,
                                                    const float* __restrict__ b2,
                                                    const float* __restrict__ bv,
                                                    const float* __restrict__ bo,
                                                    const float* __restrict__ bp,
                                                    int E) {
    __shared__ float WpS[HDIM * 8], R1S[HDIM * 8], R2S[HDIM * 8], MS[HDIM * 8];
    __shared__ float sclS[HDIM], shfS[HDIM];
    int t = threadIdx.x;

    for (int i = t; i < HDIM * 8; i += 256) WpS[i] = Wp[i];
    __syncthreads();
    fold_rows(Wo, WpS, R1S);   __syncthreads();   // R1 = Wo @ Wp
    fold_rows(Wv, R1S, R2S);   __syncthreads();   // R2 = Wv @ R1
    fold_rows(nW2, R2S, MS);   __syncthreads();   // M  = nW2 @ R2

    // BN stats reduce
    float s = 0.f, q = 0.f;
#pragma unroll 8
    for (int b = 0; b < NBLKA; b++) {
        float2 p = g_ps[b * HDIM + t];
        s += p.x; q += p.y;
    }
    float invE = 1.0f / (float)E;
    float mu = s * invE;
    float var = fmaxf(q * invE - mu * mu, 0.f);
    float scl = gamma[t] * rsqrtf(var + 1e-5f);
    sclS[t] = scl;
    shfS[t] = beta[t] - mu * scl;
    __syncthreads();

    // c2[d]: warp w<8 handles d=w
    int w = t >> 5, lane = t & 31;
    if (w < DDIM) {
        float r = 0.f;
#pragma unroll
        for (int i = 0; i < 8; i++) {
            int h = lane + 32 * i;
            r += shfS[h] * MS[h * 8 + w] + __ldg(b2 + h) * R2S[h * 8 + w]
               + __ldg(bv + h) * R1S[h * 8 + w] + __ldg(bo + h) * WpS[h * 8 + w];
        }
#pragma unroll
        for (int off = 16; off; off >>= 1) r += __shfl_xor_sync(0xffffffffu, r, off);
        if (lane == 0) g_c2[w] = 0.5f * (__ldg(bp + w) + r);
    }

    // B-fragment packing (m16n8k8 tf32, B col-major frag):
    //   b0 = B[k = l%4][n = l/4], b1 = B[k = l%4 + 4][n = l/4]
    for (int idx = t; idx < 1024; idx += 256) {
        int j = idx >> 5, l = idx & 31;
        int n = 8 * j + (l >> 2);
        int k0 = l & 3;
        g_zB[idx] = make_float2(0.5f * nW1[k0 * HDIM + n],
                                0.5f * nW1[(k0 + 4) * HDIM + n]);
        int h0 = 8 * j + k0, h1 = h0 + 4;
        int d = l >> 2;
        g_mB[idx] = make_float2(0.5f * sclS[h0] * MS[h0 * 8 + d],
                                0.5f * sclS[h1] * MS[h1 * 8 + d]);
    }
}

// ------------------------- pass B: tensor-core main ------------------------
__global__ void __launch_bounds__(256) main_kernel(const float* __restrict__ edge_attr,
                                                   const float* __restrict__ nf,
                                                   const int* __restrict__ ei0,
                                                   const int* __restrict__ ei1,
                                                   const float* __restrict__ b1,
                                                   float* __restrict__ out,
                                                   int E, int ntiles) {
    __shared__ float2 zB[1024];
    __shared__ float2 mB[1024];
    __shared__ float b1s[HDIM];
    __shared__ float ncs[8][16 * 10];   // per-warp nc tile, pad-10 rows
    int t = threadIdx.x;
    for (int i = t; i < 1024; i += 256) { zB[i] = g_zB[i]; mB[i] = g_mB[i]; }
    b1s[t] = b1[t];
    __syncthreads();

    int w = t >> 5, lane = t & 31;
    int g = lane >> 2, c = lane & 3;
    int src1 = (lane & ~3) | (c >> 1);
    int src2 = src1 + 2;
    bool odd = (lane & 1);
    float czl = g_c2[2 * c], czh = g_c2[2 * c + 1];
    float* nw = ncs[w];
    const float4* nfp = (const float4*)nf;

    int tile0 = (blockIdx.x * 8 + w) * TPW;
#pragma unroll 1
    for (int tt = 0; tt < TPW; tt++) {
        int tile = tile0 + tt;
        if (tile >= ntiles) break;
        int base = tile * 16;

        __syncwarp();
        if (lane < 16) {
            int e = min(base + lane, E - 1);
            int si = __ldg(ei0 + e), ti = __ldg(ei1 + e);
            float4 s0 = __ldg(nfp + 2 * si), s1 = __ldg(nfp + 2 * si + 1);
            float4 t0 = __ldg(nfp + 2 * ti), t1 = __ldg(nfp + 2 * ti + 1);
            float2* p = (float2*)(nw + lane * 10);
            p[0] = make_float2(s0.x + t0.x, s0.y + t0.y);
            p[1] = make_float2(s0.z + t0.z, s0.w + t0.w);
            p[2] = make_float2(s1.x + t1.x, s1.y + t1.y);
            p[3] = make_float2(s1.z + t1.z, s1.w + t1.w);
        }
        __syncwarp();

        // A-fragment for z GEMM (same for all 32 chunks): rows g/g+8, cols c/c+4
        u32 A0 = __float_as_uint(nw[g * 10 + c]);
        u32 A1 = __float_as_uint(nw[(g + 8) * 10 + c]);
        u32 A2 = __float_as_uint(nw[g * 10 + c + 4]);
        u32 A3 = __float_as_uint(nw[(g + 8) * 10 + c + 4]);

        float o0 = 0.f, o1 = 0.f, o2 = 0.f, o3 = 0.f;
#pragma unroll
        for (int j = 0; j < 32; j++) {
            float2 cb = *(const float2*)(b1s + 8 * j + 2 * c);   // bias as C operand
            float2 wz = zB[j * 32 + lane];
            u32 wz0 = __float_as_uint(wz.x), wz1 = __float_as_uint(wz.y);
            float z0, z1, z2, z3;
            asm volatile(
                "mma.sync.aligned.m16n8k8.row.col.f32.tf32.tf32.f32 "
                "{%0,%1,%2,%3}, {%4,%5,%6,%7}, {%8,%9}, {%10,%11,%12,%13};\n"
                : "=f"(z0), "=f"(z1), "=f"(z2), "=f"(z3)
                : "r"(A0), "r"(A1), "r"(A2), "r"(A3),
                  "r"(wz0), "r"(wz1),
                  "f"(cb.x), "f"(cb.y), "f"(cb.x), "f"(cb.y));
            float h0 = fmaxf(z0, 0.f), h1v = fmaxf(z1, 0.f);
            float h2 = fmaxf(z2, 0.f), h3v = fmaxf(z3, 0.f);
            // C-frag (rows g/g+8, cols 2c/2c+1) -> A-frag (rows g/g+8, cols c/c+4)
            float x0 = __shfl_sync(0xffffffffu, h0, src1);
            float x1 = __shfl_sync(0xffffffffu, h1v, src1);
            float y0 = __shfl_sync(0xffffffffu, h2, src1);
            float y1 = __shfl_sync(0xffffffffu, h3v, src1);
            float x2 = __shfl_sync(0xffffffffu, h0, src2);
            float x3 = __shfl_sync(0xffffffffu, h1v, src2);
            float y2 = __shfl_sync(0xffffffffu, h2, src2);
            float y3 = __shfl_sync(0xffffffffu, h3v, src2);
            u32 B0 = __float_as_uint(odd ? x1 : x0);
            u32 B1 = __float_as_uint(odd ? y1 : y0);
            u32 B2 = __float_as_uint(odd ? x3 : x2);
            u32 B3 = __float_as_uint(odd ? y3 : y2);
            float2 wm = mB[j * 32 + lane];
            u32 wm0 = __float_as_uint(wm.x), wm1 = __float_as_uint(wm.y);
            asm volatile(
                "mma.sync.aligned.m16n8k8.row.col.f32.tf32.tf32.f32 "
                "{%0,%1,%2,%3}, {%4,%5,%6,%7}, {%8,%9}, {%0,%1,%2,%3};\n"
                : "+f"(o0), "+f"(o1), "+f"(o2), "+f"(o3)
                : "r"(B0), "r"(B1), "r"(B2), "r"(B3),
                  "r"(wm0), "r"(wm1));
        }

        // epilogue: C-frag cols 2c,2c+1 of edges base+g, base+g+8
        int eL = base + g, eH = base + g + 8;
        if (eL < E) {
            float2 ea = *(const float2*)(edge_attr + eL * 8 + 2 * c);
            *(float2*)(out + eL * 8 + 2 * c) =
                make_float2(ea.x + o0 + czl, ea.y + o1 + czh);
        }
        if (eH < E) {
            float2 ea = *(const float2*)(edge_attr + eH * 8 + 2 * c);
            *(float2*)(out + eH * 8 + 2 * c) =
                make_float2(ea.x + o2 + czl, ea.y + o3 + czh);
        }
    }
}

// ------------------------- launch ------------------------------------------
extern "C" void kernel_launch(void* const* d_in, const int* in_sizes, int n_in,
                              void* d_out, int out_size) {
    const float* edge_attr = (const float*)d_in[0];
    const float* nf        = (const float*)d_in[1];
    const int*   ei        = (const int*)  d_in[2];
    // d_in[3..8] = edge encoder params: dead code in the reference, unused.
    const float* nW1   = (const float*)d_in[9];
    const float* nb1   = (const float*)d_in[10];
    const float* ngam  = (const float*)d_in[11];
    const float* nbet  = (const float*)d_in[12];
    const float* nW2   = (const float*)d_in[13];
    const float* nb2   = (const float*)d_in[14];
    const float* Wv    = (const float*)d_in[15];
    const float* bv    = (const float*)d_in[16];
    const float* Wo    = (const float*)d_in[17];
    const float* bo    = (const float*)d_in[18];
    const float* Wp    = (const float*)d_in[19];
    const float* bp    = (const float*)d_in[20];
    (void)n_in; (void)out_size;

    int E = in_sizes[0] / DDIM;
    const int* ei0 = ei;
    const int* ei1 = ei + E;
    float* out = (float*)d_out;

    // BN statistics (longest chain starts immediately)
    stats_kernel<<<NBLKA, 256>>>(nf, ei0, ei1, nW1, nb1, E);

    // folds + finalize + fragment packing in one single-block kernel
    setup_kernel<<<1, 256>>>(Wo, Wp, Wv, nW2, nW1, ngam, nbet,
                             nb2, bv, bo, bp, E);

    // tensor-core main pass: 16-edge tiles, TPW per warp, 8 warps/block
    int ntiles = (E + 15) / 16;
    int blocks = (ntiles + 8 * TPW - 1) / (8 * TPW);
    main_kernel<<<blocks, 256>>>(edge_attr, nf, ei0, ei1, nb1, out, E, ntiles);
}